// round 1
// baseline (speedup 1.0000x reference)
#include <cuda_runtime.h>

typedef unsigned long long ull;

// ---------------- scratch (no allocation allowed; __device__ globals) --------
__device__ float g_qp[32 * 1024];              // query @ W2  [B][H]
__device__ float g_ctx_part[16 * 32 * 1024];   // context partials [j][B][D]

// ---------------- helpers ----------------------------------------------------
__device__ __forceinline__ ull pack2(float lo, float hi) {
    ull r;
    asm("mov.b64 %0, {%1, %2};" : "=l"(r) : "f"(lo), "f"(hi));
    return r;
}
__device__ __forceinline__ void fma2(ull& d, ull a, ull b) {
    // packed fp32x2 FMA (sm_100+): d = a * b + d, per-lane IEEE fp32
    asm("fma.rn.f32x2 %0, %1, %2, %0;" : "+l"(d) : "l"(a), "l"(b));
}
__device__ __forceinline__ float2 unpk(ull p) {
    float2 f;
    asm("mov.b64 {%0, %1}, %2;" : "=f"(f.x), "=f"(f.y) : "l"(p));
    return f;
}
// accurate-enough tanh via MUFU ex2/rcp (err ~1e-6; hw tanh.approx too sloppy)
__device__ __forceinline__ float tanh_fast(float x) {
    float e = __expf(2.0f * x);
    return 1.0f - __fdividef(2.0f, e + 1.0f);
}

// ---------------- K1: query_proj = query @ W2  [32,1024] ---------------------
__global__ void qp_kernel(const float* __restrict__ query,
                          const float* __restrict__ W2) {
    __shared__ float sq[1024];
    int b = blockIdx.x;
    for (int i = threadIdx.x; i < 1024; i += 256) sq[i] = query[b * 1024 + i];
    __syncthreads();
    int h4 = threadIdx.x * 4;
    float4 acc = make_float4(0.f, 0.f, 0.f, 0.f);
#pragma unroll 4
    for (int d = 0; d < 1024; d++) {
        float q = sq[d];
        float4 wv = *(const float4*)(W2 + (size_t)d * 1024 + h4);
        acc.x += q * wv.x; acc.y += q * wv.y; acc.z += q * wv.z; acc.w += q * wv.w;
    }
    *(float4*)(g_qp + b * 1024 + h4) = acc;
}

// ---------------- K2: fused  scores = tanh(values@W1 + qp) . v ---------------
// 128x128x8 fp32 tile GEMM, f32x2 packed FMA, H looped inside the block so the
// [B,S,H] intermediate never exists; per-row score accumulated in registers.
__global__ __launch_bounds__(256, 2)
void scores_kernel(const float* __restrict__ values,
                   const float* __restrict__ W1,
                   const float* __restrict__ v,
                   float* __restrict__ scores) {
    __shared__ float As[8][128];      // values tile, transposed (K-major)
    __shared__ float Bs[8][128];      // W1 tile
    __shared__ float qv_s[128];
    __shared__ float vv_s[128];
    __shared__ float red[128][17];    // score reduction (pad 17: no conflicts)

    const int tid  = threadIdx.x;
    const int row0 = blockIdx.x * 128;          // 512 blocks, rows within one b
    const int b    = row0 >> 11;
    const float* A  = values + (size_t)row0 * 1024;
    const float* qp = g_qp + b * 1024;

    const int tx  = tid & 15, ty = tid >> 4;
    const int tx4 = tx * 4,  ty4 = ty * 4;
    const int arow = tid >> 1, acol = (tid & 1) * 4;   // A-tile load map
    const int brow = tid >> 5, bcol = (tid & 31) * 4;  // B-tile load map

    float srow[8];
#pragma unroll
    for (int i = 0; i < 8; i++) srow[i] = 0.f;

    for (int n0 = 0; n0 < 1024; n0 += 128) {
        __syncthreads();  // previous epilogue done with qv_s/vv_s
        if (tid < 128) { qv_s[tid] = qp[n0 + tid]; vv_s[tid] = v[n0 + tid]; }

        ull acc[8][4];
#pragma unroll
        for (int i = 0; i < 8; i++)
#pragma unroll
            for (int j = 0; j < 4; j++) acc[i][j] = 0ull;

        const float* Bp = W1 + n0;
        for (int k0 = 0; k0 < 1024; k0 += 8) {
            float4 av = *(const float4*)(A + (size_t)arow * 1024 + k0 + acol);
            float4 bv = *(const float4*)(Bp + (size_t)(k0 + brow) * 1024 + bcol);
            __syncthreads();
            As[acol + 0][arow] = av.x;
            As[acol + 1][arow] = av.y;
            As[acol + 2][arow] = av.z;
            As[acol + 3][arow] = av.w;
            *(float4*)&Bs[brow][bcol] = bv;
            __syncthreads();
#pragma unroll
            for (int kk = 0; kk < 8; kk++) {
                float4 aA = *(const float4*)&As[kk][ty4];
                float4 aB = *(const float4*)&As[kk][64 + ty4];
                ulonglong2 bA = *(const ulonglong2*)&Bs[kk][tx4];       // col pairs, free
                ulonglong2 bB = *(const ulonglong2*)&Bs[kk][64 + tx4];
                float ar[8] = {aA.x, aA.y, aA.z, aA.w, aB.x, aB.y, aB.z, aB.w};
#pragma unroll
                for (int i = 0; i < 8; i++) {
                    ull ad = pack2(ar[i], ar[i]);
                    fma2(acc[i][0], ad, bA.x);
                    fma2(acc[i][1], ad, bA.y);
                    fma2(acc[i][2], ad, bB.x);
                    fma2(acc[i][3], ad, bB.y);
                }
            }
        }
        // epilogue: tanh(acc + qp) * v, fold into per-row score accumulators
#pragma unroll
        for (int jp = 0; jp < 4; jp++) {
            int c0 = (jp < 2) ? (tx4 + jp * 2) : (64 + tx4 + (jp - 2) * 2);
            float q0 = qv_s[c0], q1 = qv_s[c0 + 1];
            float v0 = vv_s[c0], v1 = vv_s[c0 + 1];
#pragma unroll
            for (int i = 0; i < 8; i++) {
                float2 p = unpk(acc[i][jp]);
                srow[i] += tanh_fast(p.x + q0) * v0 + tanh_fast(p.y + q1) * v1;
            }
        }
    }

    // deterministic cross-thread score reduction
    __syncthreads();
#pragma unroll
    for (int i = 0; i < 8; i++) {
        int r = (i < 4) ? (ty4 + i) : (64 + ty4 + i - 4);
        red[r][tx] = srow[i];
    }
    __syncthreads();
    if (tid < 128) {
        float s = 0.f;
#pragma unroll
        for (int x = 0; x < 16; x++) s += red[tid][x];
        scores[row0 + tid] = s;
    }
}

// ---------------- K3: softmax over S (in-place in the output buffer) ---------
__global__ void softmax_kernel(float* __restrict__ w) {
    int b = blockIdx.x;
    float* p = w + b * 2048;
    int t = threadIdx.x;                       // 1024 threads, 2 elems each
    __shared__ float sm[32];

    float a0 = p[t], a1 = p[t + 1024];
    float m = fmaxf(a0, a1);
#pragma unroll
    for (int o = 16; o; o >>= 1) m = fmaxf(m, __shfl_xor_sync(0xffffffffu, m, o));
    if ((t & 31) == 0) sm[t >> 5] = m;
    __syncthreads();
    if (t < 32) {
        float mm = sm[t];
#pragma unroll
        for (int o = 16; o; o >>= 1) mm = fmaxf(mm, __shfl_xor_sync(0xffffffffu, mm, o));
        sm[t] = mm;
    }
    __syncthreads();
    m = sm[0];
    __syncthreads();

    float e0 = __expf(a0 - m), e1 = __expf(a1 - m);
    float s = e0 + e1;
#pragma unroll
    for (int o = 16; o; o >>= 1) s += __shfl_xor_sync(0xffffffffu, s, o);
    if ((t & 31) == 0) sm[t >> 5] = s;
    __syncthreads();
    if (t < 32) {
        float ss = sm[t];
#pragma unroll
        for (int o = 16; o; o >>= 1) ss += __shfl_xor_sync(0xffffffffu, ss, o);
        sm[t] = ss;
    }
    __syncthreads();
    float inv = 1.0f / sm[0];
    p[t] = e0 * inv;
    p[t + 1024] = e1 * inv;
}

// ---------------- K4/K5: context = w @ values (two-stage, deterministic) -----
__global__ void ctx_part_kernel(const float* __restrict__ values,
                                const float* __restrict__ w) {
    int b = blockIdx.x, j = blockIdx.y;
    __shared__ float ws[128];
    int t = threadIdx.x;                       // 256 threads cover D via float4
    if (t < 128) ws[t] = w[b * 2048 + j * 128 + t];
    __syncthreads();
    const float* V = values + ((size_t)(b * 2048 + j * 128)) * 1024 + t * 4;
    float4 acc = make_float4(0.f, 0.f, 0.f, 0.f);
#pragma unroll 8
    for (int s = 0; s < 128; s++) {
        float4 x = *(const float4*)(V + (size_t)s * 1024);
        float c = ws[s];
        acc.x += c * x.x; acc.y += c * x.y; acc.z += c * x.z; acc.w += c * x.w;
    }
    *(float4*)&g_ctx_part[((size_t)j * 32 + b) * 1024 + t * 4] = acc;
}

__global__ void ctx_reduce_kernel(float* __restrict__ ctx) {
    int b = blockIdx.x, t = threadIdx.x;       // 256 threads
    float4 acc = make_float4(0.f, 0.f, 0.f, 0.f);
#pragma unroll
    for (int j = 0; j < 16; j++) {
        float4 x = *(const float4*)&g_ctx_part[((size_t)j * 32 + b) * 1024 + t * 4];
        acc.x += x.x; acc.y += x.y; acc.z += x.z; acc.w += x.w;
    }
    *(float4*)(ctx + b * 1024 + t * 4) = acc;
}

// ---------------- launch ------------------------------------------------------
extern "C" void kernel_launch(void* const* d_in, const int* in_sizes, int n_in,
                              void* d_out, int out_size) {
    const float* query  = (const float*)d_in[0];   // [32,1024]
    const float* values = (const float*)d_in[1];   // [32,2048,1024]
    const float* W1     = (const float*)d_in[2];   // [1024,1024]
    const float* W2     = (const float*)d_in[3];   // [1024,1024]
    const float* v      = (const float*)d_in[4];   // [1024]

    float* ctx     = (float*)d_out;                // [32,1024]
    float* weights = (float*)d_out + 32 * 1024;    // [32,2048]

    qp_kernel<<<32, 256>>>(query, W2);
    scores_kernel<<<512, 256>>>(values, W1, v, weights);
    softmax_kernel<<<32, 1024>>>(weights);
    ctx_part_kernel<<<dim3(32, 16), 256>>>(values, weights);
    ctx_reduce_kernel<<<32, 256>>>(ctx);
}